// round 16
// baseline (speedup 1.0000x reference)
#include <cuda_runtime.h>
#include <cuda_fp16.h>

#define M_NODES 100000
#define HID     256
#define NREL    6
#define EPR     100000
#define NEDGE   (NREL * EPR)        // 600000
#define NMSG    1792                // 6*256 rel msgs + 256 self
#define NGRAPH  128

#define BM 128
#define BN 128
#define BK 64
#define NCHUNK (HID / BK)           // 4
#define GSMEM  (2 * (BM + BN) * BK * 2)   // 65536 (2-stage)

#define SCAN_BLK 1024
#define NSCAN1 ((M_NODES + SCAN_BLK - 1) / SCAN_BLK)  // 98
#define NBIN2  (NREL * M_NODES)                        // 600000
#define NSCAN2 ((NBIN2 + SCAN_BLK - 1) / SCAN_BLK)     // 586

// ---------------- scratch (device globals; no allocation allowed) ----------------
__device__ __half  g_hA16[(size_t)M_NODES * HID];
__device__ __half  g_hB16[(size_t)M_NODES * HID];
__device__ __half  g_msg[(size_t)M_NODES * NMSG];      // 358.4 MB
__device__ __half  g_Wt0[NMSG * HID];
__device__ __half  g_Wt1[NMSG * HID];
__device__ float   g_invdeg[M_NODES];
__device__ int     g_deg[M_NODES];
__device__ int     g_off[M_NODES + 1];
__device__ int     g_bsum1[NSCAN1];
__device__ int     g_bbase1[NSCAN1];
__device__ int     g_cursor[M_NODES];
__device__ int     g_eidx[NEDGE];                      // packed (src<<3)|r, grouped by tgt
__device__ int     g_flag[NBIN2];                      // (rel,node) has >=1 outgoing edge
__device__ int     g_soff[NBIN2 + 1];                  // exclusive scan of flags
__device__ int     g_bsum2[NSCAN2];
__device__ int     g_bbase2[NSCAN2];
__device__ int     g_rowlist[NBIN2];                   // active nodes, grouped by rel
__device__ float   g_pooled[NGRAPH * HID];
__device__ int     g_counts[NGRAPH];

// ---------------- PTX helpers (baseline ISA; nothing 'a'-gated) ----------------
__device__ __forceinline__ unsigned su32(const void* p) {
    return (unsigned)__cvta_generic_to_shared(p);
}
__device__ __forceinline__ void cp16(void* sm, const void* gm) {
    asm volatile("cp.async.cg.shared.global [%0], [%1], 16;" :: "r"(su32(sm)), "l"(gm));
}
#define CP_COMMIT() asm volatile("cp.async.commit_group;" ::: "memory")
#define CP_WAIT(n)  asm volatile("cp.async.wait_group %0;" :: "n"(n) : "memory")

__device__ __forceinline__ void ldsm4(unsigned* r, unsigned addr) {
    asm volatile("ldmatrix.sync.aligned.m8n8.x4.shared.b16 {%0,%1,%2,%3}, [%4];"
                 : "=r"(r[0]), "=r"(r[1]), "=r"(r[2]), "=r"(r[3]) : "r"(addr));
}
__device__ __forceinline__ void mma16816(float* c, const unsigned* a, unsigned b0, unsigned b1) {
    asm volatile("mma.sync.aligned.m16n8k16.row.col.f32.f16.f16.f32 "
                 "{%0,%1,%2,%3}, {%4,%5,%6,%7}, {%8,%9}, {%0,%1,%2,%3};"
                 : "+f"(c[0]), "+f"(c[1]), "+f"(c[2]), "+f"(c[3])
                 : "r"(a[0]), "r"(a[1]), "r"(a[2]), "r"(a[3]), "r"(b0), "r"(b1));
}
__device__ __forceinline__ unsigned swz(unsigned off) {
    return off ^ ((off >> 3) & 0x70);
}

// ---------------- small kernels ----------------
__global__ void embed_kernel(const int* __restrict__ x_type, const int* __restrict__ x_sub,
                             const float* __restrict__ temb, const float* __restrict__ semb,
                             __half* __restrict__ h0)
{
    int gid = blockIdx.x * 256 + threadIdx.x;
    if (gid < M_NODES * HID) {
        int n = gid >> 8, c = gid & 255;
        float v = (c < 128) ? temb[x_type[n] * 128 + c] : semb[x_sub[n] * 128 + (c - 128)];
        h0[gid] = __float2half_rn(v);
    }
}

__global__ void degflag_kernel(const int* __restrict__ edges, int* __restrict__ deg,
                               int* __restrict__ flag)
{
    int i = blockIdx.x * 256 + threadIdx.x;
    if (i < NEDGE) {
        int r = i / EPR, e = i % EPR;
        int src = edges[r * 2 * EPR + e];
        int tgt = edges[r * 2 * EPR + EPR + e];
        atomicAdd(&deg[tgt], 1);
        flag[r * M_NODES + src] = 1;
    }
}

__global__ void invdeg_kernel(const int* __restrict__ deg, float* __restrict__ invd)
{
    int i = blockIdx.x * 256 + threadIdx.x;
    if (i < M_NODES) {
        int d = deg[i];
        invd[i] = 1.0f / (float)(d > 1 ? d : 1);
    }
}

// ---- generic 3-phase exclusive scan ----
__global__ void blocksum_kernel(const int* __restrict__ v_in, int* __restrict__ bsum, int n)
{
    __shared__ int ws[32];
    int i = blockIdx.x * SCAN_BLK + threadIdx.x;
    int v = (i < n) ? v_in[i] : 0;
#pragma unroll
    for (int o = 16; o; o >>= 1) v += __shfl_down_sync(0xffffffff, v, o);
    if ((threadIdx.x & 31) == 0) ws[threadIdx.x >> 5] = v;
    __syncthreads();
    if (threadIdx.x < 32) {
        int s = ws[threadIdx.x];
#pragma unroll
        for (int o = 16; o; o >>= 1) s += __shfl_down_sync(0xffffffff, s, o);
        if (threadIdx.x == 0) bsum[blockIdx.x] = s;
    }
}

__global__ void bscan_kernel(const int* __restrict__ bsum, int* __restrict__ bbase, int n)
{
    __shared__ int wsum[32];
    __shared__ int wbase[32];
    int tid = threadIdx.x, lane = tid & 31, wid = tid >> 5;
    int v = (tid < n) ? bsum[tid] : 0;
    int x = v;
#pragma unroll
    for (int o = 1; o < 32; o <<= 1) {
        int t = __shfl_up_sync(0xffffffff, x, o);
        if (lane >= o) x += t;
    }
    if (lane == 31) wsum[wid] = x;
    __syncthreads();
    if (wid == 0) {
        int s = wsum[lane];
        int y = s;
#pragma unroll
        for (int o = 1; o < 32; o <<= 1) {
            int t = __shfl_up_sync(0xffffffff, y, o);
            if (lane >= o) y += t;
        }
        wbase[lane] = y - s;
    }
    __syncthreads();
    if (tid < n) bbase[tid] = wbase[wid] + x - v;
}

__global__ void offsets_kernel(const int* __restrict__ v_in, const int* __restrict__ bbase,
                               int* __restrict__ off, int n)
{
    __shared__ int wsum[32];
    __shared__ int wbase[32];
    int i = blockIdx.x * SCAN_BLK + threadIdx.x;
    int lane = threadIdx.x & 31, wid = threadIdx.x >> 5;
    int v = (i < n) ? v_in[i] : 0;
    int x = v;
#pragma unroll
    for (int o = 1; o < 32; o <<= 1) {
        int t = __shfl_up_sync(0xffffffff, x, o);
        if (lane >= o) x += t;
    }
    if (lane == 31) wsum[wid] = x;
    __syncthreads();
    if (wid == 0) {
        int s = wsum[lane];
        int y = s;
#pragma unroll
        for (int o = 1; o < 32; o <<= 1) {
            int t = __shfl_up_sync(0xffffffff, y, o);
            if (lane >= o) y += t;
        }
        wbase[lane] = y - s;
    }
    __syncthreads();
    if (i < n) off[i] = bbase[blockIdx.x] + wbase[wid] + x - v;
    if (i == n - 1) off[n] = bbase[blockIdx.x] + wbase[wid] + x;
}

__global__ void fill_kernel(const int* __restrict__ edges, const int* __restrict__ off,
                            int* __restrict__ cursor, int* __restrict__ eidx)
{
    int i = blockIdx.x * 256 + threadIdx.x;
    if (i < NEDGE) {
        int r = i / EPR, e = i % EPR;
        int src = edges[r * 2 * EPR + e];
        int tgt = edges[r * 2 * EPR + EPR + e];
        int slot = off[tgt] + atomicAdd(&cursor[tgt], 1);
        eidx[slot] = (src << 3) | r;
    }
}

__global__ void rowlist_kernel(const int* __restrict__ flag, const int* __restrict__ soff,
                               int* __restrict__ rowlist)
{
    int i = blockIdx.x * 256 + threadIdx.x;
    if (i < NBIN2 && flag[i])
        rowlist[soff[i]] = i % M_NODES;
}

__global__ void convW_kernel(const float* __restrict__ Wrel, const float* __restrict__ Wself,
                             __half* __restrict__ Wt)
{
    int idx = blockIdx.x * 256 + threadIdx.x;
    if (idx < NMSG * HID) {
        int n = idx >> 8, k = idx & 255;
        float v = (n < 1536) ? Wrel[(((n >> 8) * 256) + k) * 256 + (n & 255)]
                             : Wself[k * 256 + (n & 255)];
        Wt[idx] = __float2half_rn(v);
    }
}

// ---------------- fused GEMM: grid (2, 782, 7); z<6 = rel (compacted), z==6 = self (dense) ----------------
__global__ __launch_bounds__(256, 2)
void gemm_all(const __half* __restrict__ A, const __half* __restrict__ Wt,
              const int* __restrict__ soff, const int* __restrict__ rowlist,
              __half* __restrict__ msg)
{
    extern __shared__ unsigned char smraw[];
    const int z     = blockIdx.z;
    const bool self = (z == NREL);
    const int m0    = blockIdx.y * BM;

    int base = 0, cnt = M_NODES;
    if (!self) {
        base = __ldg(&soff[z * M_NODES]);
        cnt  = __ldg(&soff[(z + 1) * M_NODES]) - base;
        if (m0 >= cnt) return;
    }

    const int tid  = threadIdx.x;
    const int lane = tid & 31;
    const int wid  = tid >> 5;
    const int wm   = wid & 3;
    const int wn   = wid >> 2;
    const int n0   = blockIdx.x * BN;
    const int wtrow0 = z * 256 + n0;

    const int lrow = tid >> 3;
    const int lseg = tid & 7;

    int amrow[4];
#pragma unroll
    for (int p = 0; p < 4; p++) {
        int idx = m0 + lrow + p * 32;
        if (idx >= cnt) idx = cnt - 1;
        amrow[p] = self ? idx : __ldg(&rowlist[base + idx]);
    }

    float acc[2][8][4];
#pragma unroll
    for (int mi = 0; mi < 2; mi++)
#pragma unroll
        for (int ni = 0; ni < 8; ni++)
#pragma unroll
            for (int j = 0; j < 4; j++) acc[mi][ni][j] = 0.0f;

    unsigned aS[2], bS[2];
    aS[0] = su32(smraw);            bS[0] = su32(smraw + 16384);
    aS[1] = su32(smraw + 32768);    bS[1] = su32(smraw + 49152);

    auto issue = [&](int c, int st) {
        int koff = c * BK;
        unsigned char* As = smraw + st * 32768;
        unsigned char* Bs = smraw + st * 32768 + 16384;
#pragma unroll
        for (int p = 0; p < 4; p++) {
            int row = lrow + p * 32;
            unsigned so = swz((unsigned)(row * 128 + lseg * 16));
            cp16(As + so, A  + (size_t)amrow[p] * HID + koff + lseg * 8);
            cp16(Bs + so, Wt + (size_t)(wtrow0 + row) * HID + koff + lseg * 8);
        }
        CP_COMMIT();
    };

    issue(0, 0);

    for (int c = 0; c < NCHUNK; ++c) {
        int st = c & 1;
        if (c + 1 < NCHUNK) { issue(c + 1, st ^ 1); CP_WAIT(1); }
        else                { CP_WAIT(0); }
        __syncthreads();

        unsigned ab = aS[st], bb = bS[st];
#pragma unroll
        for (int ks = 0; ks < 4; ++ks) {
            unsigned a[2][4], b[4][4];
#pragma unroll
            for (int mi = 0; mi < 2; mi++) {
                int row = wm * 32 + mi * 16 + (lane & 15);
                unsigned off = (unsigned)(row * 128 + ks * 32 + (lane >> 4) * 16);
                ldsm4(a[mi], ab + swz(off));
            }
#pragma unroll
            for (int nj = 0; nj < 4; nj++) {
                int q = lane >> 3, r2 = lane & 7;
                int nrow = wn * 64 + nj * 16 + (q >> 1) * 8 + r2;
                unsigned off = (unsigned)(nrow * 128 + ks * 32 + (q & 1) * 16);
                ldsm4(b[nj], bb + swz(off));
            }
#pragma unroll
            for (int mi = 0; mi < 2; mi++)
#pragma unroll
                for (int ni = 0; ni < 8; ni++)
                    mma16816(acc[mi][ni], a[mi], b[ni >> 1][(ni & 1) * 2], b[ni >> 1][(ni & 1) * 2 + 1]);
        }
        __syncthreads();
    }

    const int cb = wtrow0 + wn * 64 + (lane & 3) * 2;
#pragma unroll
    for (int mi = 0; mi < 2; mi++) {
        int r0 = m0 + wm * 32 + mi * 16 + (lane >> 2);
        int r1 = r0 + 8;
        if (r0 < cnt) {
            int grow = self ? r0 : __ldg(&rowlist[base + r0]);
            __half* dst = msg + (size_t)grow * NMSG + cb;
#pragma unroll
            for (int ni = 0; ni < 8; ni++)
                __stcs((__half2*)(dst + ni * 8), __floats2half2_rn(acc[mi][ni][0], acc[mi][ni][1]));
        }
        if (r1 < cnt) {
            int grow = self ? r1 : __ldg(&rowlist[base + r1]);
            __half* dst = msg + (size_t)grow * NMSG + cb;
#pragma unroll
            for (int ni = 0; ni < 8; ni++)
                __stcs((__half2*)(dst + ni * 8), __floats2half2_rn(acc[mi][ni][2], acc[mi][ni][3]));
        }
    }
}

// ---------------- gather + combine (R11 layout): warp per node, x4 unroll, default-cache loads ----------------
__global__ __launch_bounds__(256)
void gather_kernel(const __half* __restrict__ msg, const int* __restrict__ off,
                   const int* __restrict__ eidx, const float* __restrict__ invd,
                   const float* __restrict__ bias, __half* __restrict__ hout)
{
    int node = blockIdx.x * 8 + (threadIdx.x >> 5);
    if (node >= M_NODES) return;
    const int lane = threadIdx.x & 31;

    int beg = __ldg(&off[node]);
    int end = __ldg(&off[node + 1]);

    float acc[8];
#pragma unroll
    for (int j = 0; j < 8; j++) acc[j] = 0.0f;

    auto accum = [&](uint4 u) {
        const __half2* h2 = (const __half2*)&u;
#pragma unroll
        for (int k = 0; k < 4; k++) {
            float2 f = __half22float2(h2[k]);
            acc[2 * k]     += f.x;
            acc[2 * k + 1] += f.y;
        }
    };
    auto rowptr = [&](int pk) {
        return (const uint4*)(msg + (size_t)(pk >> 3) * NMSG + (pk & 7) * HID + lane * 8);
    };

    int e = beg;
    for (; e + 3 < end; e += 4) {
        uint4 u0 = __ldg(rowptr(__ldg(&eidx[e])));
        uint4 u1 = __ldg(rowptr(__ldg(&eidx[e + 1])));
        uint4 u2 = __ldg(rowptr(__ldg(&eidx[e + 2])));
        uint4 u3 = __ldg(rowptr(__ldg(&eidx[e + 3])));
        accum(u0); accum(u1); accum(u2); accum(u3);
    }
    for (; e < end; ++e)
        accum(__ldg(rowptr(__ldg(&eidx[e]))));

    float w = invd[node];
    uint4 s = __ldg((const uint4*)(msg + (size_t)node * NMSG + 1536 + lane * 8));
    const __half2* s2 = (const __half2*)&s;
    float4 b0 = *(const float4*)(bias + lane * 8);
    float4 b1 = *(const float4*)(bias + lane * 8 + 4);
    float bb[8] = {b0.x, b0.y, b0.z, b0.w, b1.x, b1.y, b1.z, b1.w};

    uint4 outv;
    __half2* o2 = (__half2*)&outv;
#pragma unroll
    for (int k = 0; k < 4; k++) {
        float2 sf = __half22float2(s2[k]);
        float v0 = fmaxf(acc[2 * k]     * w + sf.x + bb[2 * k],     0.f);
        float v1 = fmaxf(acc[2 * k + 1] * w + sf.y + bb[2 * k + 1], 0.f);
        o2[k] = __floats2half2_rn(v0, v1);
    }
    *(uint4*)(hout + (size_t)node * HID + lane * 8) = outv;
}

// ---------------- pooling + MLP ----------------
__global__ void count_kernel(const int* __restrict__ bids, int* __restrict__ counts)
{
    int g = threadIdx.x;
    if (g >= NGRAPH) return;
    int lo = 0, hi = M_NODES;
    while (lo < hi) { int mid = (lo + hi) >> 1; if (bids[mid] < g) lo = mid + 1; else hi = mid; }
    int start = lo;
    lo = 0; hi = M_NODES;
    while (lo < hi) { int mid = (lo + hi) >> 1; if (bids[mid] <= g) lo = mid + 1; else hi = mid; }
    counts[g] = lo - start;
}

__global__ void pool_sum_kernel(const __half* __restrict__ h, const int* __restrict__ bids,
                                float* __restrict__ pooled)
{
    int c = threadIdx.x;
    int n_start = blockIdx.x * 256;
    int n_end = n_start + 256;
    if (n_end > M_NODES) n_end = M_NODES;
    if (n_start >= M_NODES) return;
    int cur = bids[n_start];
    float acc = 0.0f;
    for (int n = n_start; n < n_end; n++) {
        int g = bids[n];
        if (g != cur) { atomicAdd(&pooled[cur * HID + c], acc); acc = 0.0f; cur = g; }
        acc += __half2float(h[(size_t)n * HID + c]);
    }
    atomicAdd(&pooled[cur * HID + c], acc);
}

__global__ void mlp_kernel(const float* __restrict__ pooled, const int* __restrict__ counts,
                           const float* __restrict__ pW1, const float* __restrict__ pb1,
                           const float* __restrict__ pW2, const float* __restrict__ pb2,
                           float* __restrict__ out)
{
    __shared__ float p[HID];
    __shared__ float t[HID];
    int g = blockIdx.x, d = threadIdx.x;
    int cn = counts[g];
    float inv = 1.0f / (float)(cn > 1 ? cn : 1);
    p[d] = pooled[g * HID + d] * inv;
    __syncthreads();
    float a = pb1[d];
#pragma unroll 8
    for (int k = 0; k < HID; k++) a += p[k] * pW1[k * HID + d];
    t[d] = a > 0.f ? a : 0.f;
    __syncthreads();
    float o = pb2[d];
#pragma unroll 8
    for (int k = 0; k < HID; k++) o += t[k] * pW2[k * HID + d];
    out[g * HID + d] = o;
}

// ---------------------------------------------------------------
extern "C" void kernel_launch(void* const* d_in, const int* in_sizes, int n_in,
                              void* d_out, int out_size)
{
    const int*   x_type = (const int*)d_in[0];
    const int*   x_sub  = (const int*)d_in[1];
    const int*   edges  = (const int*)d_in[2];
    const int*   bids   = (const int*)d_in[3];
    const float* temb   = (const float*)d_in[5];
    const float* semb   = (const float*)d_in[6];
    const float* Wrel0  = (const float*)d_in[7];
    const float* Wself0 = (const float*)d_in[8];
    const float* b0     = (const float*)d_in[9];
    const float* Wrel1  = (const float*)d_in[10];
    const float* Wself1 = (const float*)d_in[11];
    const float* b1     = (const float*)d_in[12];
    const float* pW1    = (const float*)d_in[13];
    const float* pb1    = (const float*)d_in[14];
    const float* pW2    = (const float*)d_in[15];
    const float* pb2    = (const float*)d_in[16];
    float* out = (float*)d_out;

    void *phA, *phB, *pmsg, *pWt0, *pWt1, *pinv, *pdeg, *poff, *pbsum1, *pbbase1, *pcur, *peidx;
    void *pflag, *psoff, *pbsum2, *pbbase2, *prowlist, *ppooled, *pcnt;
    cudaGetSymbolAddress(&phA, g_hA16);
    cudaGetSymbolAddress(&phB, g_hB16);
    cudaGetSymbolAddress(&pmsg, g_msg);
    cudaGetSymbolAddress(&pWt0, g_Wt0);
    cudaGetSymbolAddress(&pWt1, g_Wt1);
    cudaGetSymbolAddress(&pinv, g_invdeg);
    cudaGetSymbolAddress(&pdeg, g_deg);
    cudaGetSymbolAddress(&poff, g_off);
    cudaGetSymbolAddress(&pbsum1, g_bsum1);
    cudaGetSymbolAddress(&pbbase1, g_bbase1);
    cudaGetSymbolAddress(&pcur, g_cursor);
    cudaGetSymbolAddress(&peidx, g_eidx);
    cudaGetSymbolAddress(&pflag, g_flag);
    cudaGetSymbolAddress(&psoff, g_soff);
    cudaGetSymbolAddress(&pbsum2, g_bsum2);
    cudaGetSymbolAddress(&pbbase2, g_bbase2);
    cudaGetSymbolAddress(&prowlist, g_rowlist);
    cudaGetSymbolAddress(&ppooled, g_pooled);
    cudaGetSymbolAddress(&pcnt, g_counts);

    cudaFuncSetAttribute(gemm_all, cudaFuncAttributeMaxDynamicSharedMemorySize, GSMEM);

    // ---- fork a side stream for graph prework (depends only on `edges`/`bids`) ----
    cudaStream_t side;
    cudaEvent_t evFork, evJoin;
    cudaStreamCreateWithFlags(&side, cudaStreamNonBlocking);
    cudaEventCreateWithFlags(&evFork, cudaEventDisableTiming);
    cudaEventCreateWithFlags(&evJoin, cudaEventDisableTiming);

    cudaEventRecord(evFork, 0);
    cudaStreamWaitEvent(side, evFork, 0);

    cudaMemsetAsync(pdeg, 0, M_NODES * sizeof(int), side);
    cudaMemsetAsync(pcur, 0, M_NODES * sizeof(int), side);
    cudaMemsetAsync(pflag, 0, NBIN2 * sizeof(int), side);
    degflag_kernel<<<(NEDGE + 255) / 256, 256, 0, side>>>(edges, (int*)pdeg, (int*)pflag);
    invdeg_kernel<<<(M_NODES + 255) / 256, 256, 0, side>>>((const int*)pdeg, (float*)pinv);
    blocksum_kernel<<<NSCAN1, SCAN_BLK, 0, side>>>((const int*)pdeg, (int*)pbsum1, M_NODES);
    bscan_kernel<<<1, SCAN_BLK, 0, side>>>((const int*)pbsum1, (int*)pbbase1, NSCAN1);
    offsets_kernel<<<NSCAN1, SCAN_BLK, 0, side>>>((const int*)pdeg, (const int*)pbbase1, (int*)poff, M_NODES);
    fill_kernel<<<(NEDGE + 255) / 256, 256, 0, side>>>(edges, (const int*)poff, (int*)pcur, (int*)peidx);
    blocksum_kernel<<<NSCAN2, SCAN_BLK, 0, side>>>((const int*)pflag, (int*)pbsum2, NBIN2);
    bscan_kernel<<<1, SCAN_BLK, 0, side>>>((const int*)pbsum2, (int*)pbbase2, NSCAN2);
    offsets_kernel<<<NSCAN2, SCAN_BLK, 0, side>>>((const int*)pflag, (const int*)pbbase2, (int*)psoff, NBIN2);
    rowlist_kernel<<<(NBIN2 + 255) / 256, 256, 0, side>>>((const int*)pflag, (const int*)psoff, (int*)prowlist);
    count_kernel<<<1, 128, 0, side>>>(bids, (int*)pcnt);
    cudaEventRecord(evJoin, side);

    // main stream: structure-independent work runs concurrently with prework
    cudaMemsetAsync(ppooled, 0, NGRAPH * HID * sizeof(float));
    embed_kernel<<<(M_NODES * HID + 255) / 256, 256>>>(x_type, x_sub, temb, semb, (__half*)phA);
    convW_kernel<<<(NMSG * HID + 255) / 256, 256>>>(Wrel0, Wself0, (__half*)pWt0);
    convW_kernel<<<(NMSG * HID + 255) / 256, 256>>>(Wrel1, Wself1, (__half*)pWt1);

    dim3 agrid(2, (M_NODES + BM - 1) / BM, NREL + 1);   // (2, 782, 7): 6 rels + self
    int gblocks = (M_NODES + 7) / 8;

    cudaStreamWaitEvent(0, evJoin, 0);   // join: fused GEMM needs rowlist; gather needs CSR

    // ---- layer 0: hA -> hB ----
    gemm_all<<<agrid, 256, GSMEM>>>((const __half*)phA, (const __half*)pWt0,
                                    (const int*)psoff, (const int*)prowlist, (__half*)pmsg);
    gather_kernel<<<gblocks, 256>>>((const __half*)pmsg, (const int*)poff, (const int*)peidx,
                                    (const float*)pinv, b0, (__half*)phB);

    // ---- layer 1: hB -> hA ----
    gemm_all<<<agrid, 256, GSMEM>>>((const __half*)phB, (const __half*)pWt1,
                                    (const int*)psoff, (const int*)prowlist, (__half*)pmsg);
    gather_kernel<<<gblocks, 256>>>((const __half*)pmsg, (const int*)poff, (const int*)peidx,
                                    (const float*)pinv, b1, (__half*)phA);

    // ---- pool + MLP ----
    pool_sum_kernel<<<(M_NODES + 255) / 256, 256>>>((const __half*)phA, bids, (float*)ppooled);
    mlp_kernel<<<NGRAPH, 256>>>((const float*)ppooled, (const int*)pcnt, pW1, pb1, pW2, pb2, out);

    cudaEventDestroy(evFork);
    cudaEventDestroy(evJoin);
    cudaStreamDestroy(side);
}

// round 17
// speedup vs baseline: 1.0352x; 1.0352x over previous
#include <cuda_runtime.h>
#include <cuda_fp16.h>

#define M_NODES 100000
#define HID     256
#define NREL    6
#define EPR     100000
#define NEDGE   (NREL * EPR)        // 600000
#define NMSG    1792                // 6*256 rel msgs + 256 self
#define NGRAPH  128

#define BM 128
#define BN 128
#define BK 64
#define NCHUNK (HID / BK)           // 4
#define GSMEM  (2 * (BM + BN) * BK * 2)   // 65536 (2-stage)

#define SCAN_BLK 1024
#define NSCAN1 ((M_NODES + SCAN_BLK - 1) / SCAN_BLK)  // 98
#define NBIN2  (NREL * M_NODES)                        // 600000
#define NSCAN2 ((NBIN2 + SCAN_BLK - 1) / SCAN_BLK)     // 586

// ---------------- scratch (device globals; no allocation allowed) ----------------
__device__ __half  g_hA16[(size_t)M_NODES * HID];
__device__ __half  g_hB16[(size_t)M_NODES * HID];
__device__ __half  g_msg[(size_t)M_NODES * NMSG];      // 358.4 MB
__device__ __half  g_Wt0[NMSG * HID];
__device__ __half  g_Wt1[NMSG * HID];
__device__ float   g_invdeg[M_NODES];
__device__ int     g_deg[M_NODES];
__device__ int     g_off[M_NODES + 1];
__device__ int     g_bsum1[NSCAN1];
__device__ int     g_bbase1[NSCAN1];
__device__ int     g_cursor[M_NODES];
__device__ int     g_eidx[NEDGE];                      // packed (src<<3)|r, grouped by tgt
__device__ int     g_flag[NBIN2];                      // (rel,node) has >=1 outgoing edge
__device__ int     g_soff[NBIN2 + 1];                  // exclusive scan of flags
__device__ int     g_bsum2[NSCAN2];
__device__ int     g_bbase2[NSCAN2];
__device__ int     g_rowlist[NBIN2];                   // active nodes, grouped by rel
__device__ float   g_pooled[NGRAPH * HID];
__device__ int     g_counts[NGRAPH];

// ---------------- PTX helpers (baseline ISA; nothing 'a'-gated) ----------------
__device__ __forceinline__ unsigned su32(const void* p) {
    return (unsigned)__cvta_generic_to_shared(p);
}
__device__ __forceinline__ void cp16(void* sm, const void* gm) {
    asm volatile("cp.async.cg.shared.global [%0], [%1], 16;" :: "r"(su32(sm)), "l"(gm));
}
#define CP_COMMIT() asm volatile("cp.async.commit_group;" ::: "memory")
#define CP_WAIT(n)  asm volatile("cp.async.wait_group %0;" :: "n"(n) : "memory")

__device__ __forceinline__ void ldsm4(unsigned* r, unsigned addr) {
    asm volatile("ldmatrix.sync.aligned.m8n8.x4.shared.b16 {%0,%1,%2,%3}, [%4];"
                 : "=r"(r[0]), "=r"(r[1]), "=r"(r[2]), "=r"(r[3]) : "r"(addr));
}
__device__ __forceinline__ void mma16816(float* c, const unsigned* a, unsigned b0, unsigned b1) {
    asm volatile("mma.sync.aligned.m16n8k16.row.col.f32.f16.f16.f32 "
                 "{%0,%1,%2,%3}, {%4,%5,%6,%7}, {%8,%9}, {%0,%1,%2,%3};"
                 : "+f"(c[0]), "+f"(c[1]), "+f"(c[2]), "+f"(c[3])
                 : "r"(a[0]), "r"(a[1]), "r"(a[2]), "r"(a[3]), "r"(b0), "r"(b1));
}
__device__ __forceinline__ unsigned swz(unsigned off) {
    return off ^ ((off >> 3) & 0x70);
}

// ---------------- small kernels ----------------
__global__ void embed_kernel(const int* __restrict__ x_type, const int* __restrict__ x_sub,
                             const float* __restrict__ temb, const float* __restrict__ semb,
                             __half* __restrict__ h0)
{
    int gid = blockIdx.x * 256 + threadIdx.x;
    if (gid < M_NODES * HID) {
        int n = gid >> 8, c = gid & 255;
        float v = (c < 128) ? temb[x_type[n] * 128 + c] : semb[x_sub[n] * 128 + (c - 128)];
        h0[gid] = __float2half_rn(v);
    }
}

__global__ void degflag_kernel(const int* __restrict__ edges, int* __restrict__ deg,
                               int* __restrict__ flag)
{
    int i = blockIdx.x * 256 + threadIdx.x;
    if (i < NEDGE) {
        int r = i / EPR, e = i % EPR;
        int src = edges[r * 2 * EPR + e];
        int tgt = edges[r * 2 * EPR + EPR + e];
        atomicAdd(&deg[tgt], 1);
        flag[r * M_NODES + src] = 1;
    }
}

__global__ void invdeg_kernel(const int* __restrict__ deg, float* __restrict__ invd)
{
    int i = blockIdx.x * 256 + threadIdx.x;
    if (i < M_NODES) {
        int d = deg[i];
        invd[i] = 1.0f / (float)(d > 1 ? d : 1);
    }
}

// ---- generic 3-phase exclusive scan ----
__global__ void blocksum_kernel(const int* __restrict__ v_in, int* __restrict__ bsum, int n)
{
    __shared__ int ws[32];
    int i = blockIdx.x * SCAN_BLK + threadIdx.x;
    int v = (i < n) ? v_in[i] : 0;
#pragma unroll
    for (int o = 16; o; o >>= 1) v += __shfl_down_sync(0xffffffff, v, o);
    if ((threadIdx.x & 31) == 0) ws[threadIdx.x >> 5] = v;
    __syncthreads();
    if (threadIdx.x < 32) {
        int s = ws[threadIdx.x];
#pragma unroll
        for (int o = 16; o; o >>= 1) s += __shfl_down_sync(0xffffffff, s, o);
        if (threadIdx.x == 0) bsum[blockIdx.x] = s;
    }
}

__global__ void bscan_kernel(const int* __restrict__ bsum, int* __restrict__ bbase, int n)
{
    __shared__ int wsum[32];
    __shared__ int wbase[32];
    int tid = threadIdx.x, lane = tid & 31, wid = tid >> 5;
    int v = (tid < n) ? bsum[tid] : 0;
    int x = v;
#pragma unroll
    for (int o = 1; o < 32; o <<= 1) {
        int t = __shfl_up_sync(0xffffffff, x, o);
        if (lane >= o) x += t;
    }
    if (lane == 31) wsum[wid] = x;
    __syncthreads();
    if (wid == 0) {
        int s = wsum[lane];
        int y = s;
#pragma unroll
        for (int o = 1; o < 32; o <<= 1) {
            int t = __shfl_up_sync(0xffffffff, y, o);
            if (lane >= o) y += t;
        }
        wbase[lane] = y - s;
    }
    __syncthreads();
    if (tid < n) bbase[tid] = wbase[wid] + x - v;
}

__global__ void offsets_kernel(const int* __restrict__ v_in, const int* __restrict__ bbase,
                               int* __restrict__ off, int n)
{
    __shared__ int wsum[32];
    __shared__ int wbase[32];
    int i = blockIdx.x * SCAN_BLK + threadIdx.x;
    int lane = threadIdx.x & 31, wid = threadIdx.x >> 5;
    int v = (i < n) ? v_in[i] : 0;
    int x = v;
#pragma unroll
    for (int o = 1; o < 32; o <<= 1) {
        int t = __shfl_up_sync(0xffffffff, x, o);
        if (lane >= o) x += t;
    }
    if (lane == 31) wsum[wid] = x;
    __syncthreads();
    if (wid == 0) {
        int s = wsum[lane];
        int y = s;
#pragma unroll
        for (int o = 1; o < 32; o <<= 1) {
            int t = __shfl_up_sync(0xffffffff, y, o);
            if (lane >= o) y += t;
        }
        wbase[lane] = y - s;
    }
    __syncthreads();
    if (i < n) off[i] = bbase[blockIdx.x] + wbase[wid] + x - v;
    if (i == n - 1) off[n] = bbase[blockIdx.x] + wbase[wid] + x;
}

__global__ void fill_kernel(const int* __restrict__ edges, const int* __restrict__ off,
                            int* __restrict__ cursor, int* __restrict__ eidx)
{
    int i = blockIdx.x * 256 + threadIdx.x;
    if (i < NEDGE) {
        int r = i / EPR, e = i % EPR;
        int src = edges[r * 2 * EPR + e];
        int tgt = edges[r * 2 * EPR + EPR + e];
        int slot = off[tgt] + atomicAdd(&cursor[tgt], 1);
        eidx[slot] = (src << 3) | r;
    }
}

__global__ void rowlist_kernel(const int* __restrict__ flag, const int* __restrict__ soff,
                               int* __restrict__ rowlist)
{
    int i = blockIdx.x * 256 + threadIdx.x;
    if (i < NBIN2 && flag[i])
        rowlist[soff[i]] = i % M_NODES;
}

__global__ void convW_kernel(const float* __restrict__ Wrel, const float* __restrict__ Wself,
                             __half* __restrict__ Wt)
{
    int idx = blockIdx.x * 256 + threadIdx.x;
    if (idx < NMSG * HID) {
        int n = idx >> 8, k = idx & 255;
        float v = (n < 1536) ? Wrel[(((n >> 8) * 256) + k) * 256 + (n & 255)]
                             : Wself[k * 256 + (n & 255)];
        Wt[idx] = __float2half_rn(v);
    }
}

// ---------------- rel GEMM: compacted rows, grid (2, 782, 6) ----------------
__global__ __launch_bounds__(256, 2)
void gemm_rel(const __half* __restrict__ A, const __half* __restrict__ Wt,
              const int* __restrict__ soff, const int* __restrict__ rowlist,
              __half* __restrict__ msg)
{
    extern __shared__ unsigned char smraw[];
    const int rrel = blockIdx.z;
    const int base = __ldg(&soff[rrel * M_NODES]);
    const int cnt  = __ldg(&soff[(rrel + 1) * M_NODES]) - base;
    const int m0   = blockIdx.y * BM;
    if (m0 >= cnt) return;

    const int tid  = threadIdx.x;
    const int lane = tid & 31;
    const int wid  = tid >> 5;
    const int wm   = wid & 3;
    const int wn   = wid >> 2;
    const int n0   = blockIdx.x * BN;

    const int lrow = tid >> 3;
    const int lseg = tid & 7;

    int amrow[4];
#pragma unroll
    for (int p = 0; p < 4; p++) {
        int idx = m0 + lrow + p * 32;
        if (idx >= cnt) idx = cnt - 1;
        amrow[p] = __ldg(&rowlist[base + idx]);
    }

    float acc[2][8][4];
#pragma unroll
    for (int mi = 0; mi < 2; mi++)
#pragma unroll
        for (int ni = 0; ni < 8; ni++)
#pragma unroll
            for (int j = 0; j < 4; j++) acc[mi][ni][j] = 0.0f;

    unsigned aS[2], bS[2];
    aS[0] = su32(smraw);            bS[0] = su32(smraw + 16384);
    aS[1] = su32(smraw + 32768);    bS[1] = su32(smraw + 49152);

    auto issue = [&](int c, int st) {
        int koff = c * BK;
        unsigned char* As = smraw + st * 32768;
        unsigned char* Bs = smraw + st * 32768 + 16384;
#pragma unroll
        for (int p = 0; p < 4; p++) {
            int row = lrow + p * 32;
            unsigned so = swz((unsigned)(row * 128 + lseg * 16));
            cp16(As + so, A  + (size_t)amrow[p] * HID + koff + lseg * 8);
            cp16(Bs + so, Wt + (size_t)(rrel * 256 + n0 + row) * HID + koff + lseg * 8);
        }
        CP_COMMIT();
    };

    issue(0, 0);

    for (int c = 0; c < NCHUNK; ++c) {
        int st = c & 1;
        if (c + 1 < NCHUNK) { issue(c + 1, st ^ 1); CP_WAIT(1); }
        else                { CP_WAIT(0); }
        __syncthreads();

        unsigned ab = aS[st], bb = bS[st];
#pragma unroll
        for (int ks = 0; ks < 4; ++ks) {
            unsigned a[2][4], b[4][4];
#pragma unroll
            for (int mi = 0; mi < 2; mi++) {
                int row = wm * 32 + mi * 16 + (lane & 15);
                unsigned off = (unsigned)(row * 128 + ks * 32 + (lane >> 4) * 16);
                ldsm4(a[mi], ab + swz(off));
            }
#pragma unroll
            for (int nj = 0; nj < 4; nj++) {
                int q = lane >> 3, r2 = lane & 7;
                int nrow = wn * 64 + nj * 16 + (q >> 1) * 8 + r2;
                unsigned off = (unsigned)(nrow * 128 + ks * 32 + (q & 1) * 16);
                ldsm4(b[nj], bb + swz(off));
            }
#pragma unroll
            for (int mi = 0; mi < 2; mi++)
#pragma unroll
                for (int ni = 0; ni < 8; ni++)
                    mma16816(acc[mi][ni], a[mi], b[ni >> 1][(ni & 1) * 2], b[ni >> 1][(ni & 1) * 2 + 1]);
        }
        __syncthreads();
    }

    const int cb = rrel * 256 + n0 + wn * 64 + (lane & 3) * 2;
#pragma unroll
    for (int mi = 0; mi < 2; mi++) {
        int r0 = m0 + wm * 32 + mi * 16 + (lane >> 2);
        int r1 = r0 + 8;
        if (r0 < cnt) {
            int grow = __ldg(&rowlist[base + r0]);
            __half* dst = msg + (size_t)grow * NMSG + cb;
#pragma unroll
            for (int ni = 0; ni < 8; ni++)
                __stcs((__half2*)(dst + ni * 8), __floats2half2_rn(acc[mi][ni][0], acc[mi][ni][1]));
        }
        if (r1 < cnt) {
            int grow = __ldg(&rowlist[base + r1]);
            __half* dst = msg + (size_t)grow * NMSG + cb;
#pragma unroll
            for (int ni = 0; ni < 8; ni++)
                __stcs((__half2*)(dst + ni * 8), __floats2half2_rn(acc[mi][ni][2], acc[mi][ni][3]));
        }
    }
}

// ---------------- self GEMM: dense rows, cols 1536..1791, grid (2, 782) ----------------
__global__ __launch_bounds__(256, 2)
void gemm_self(const __half* __restrict__ A, const __half* __restrict__ Wt,
               __half* __restrict__ msg)
{
    extern __shared__ unsigned char smraw[];
    const int tid  = threadIdx.x;
    const int lane = tid & 31;
    const int wid  = tid >> 5;
    const int wm   = wid & 3;
    const int wn   = wid >> 2;
    const int m0   = blockIdx.y * BM;
    const int n0   = blockIdx.x * BN;

    const int lrow = tid >> 3;
    const int lseg = tid & 7;

    int amrow[4];
#pragma unroll
    for (int p = 0; p < 4; p++) {
        int m = m0 + lrow + p * 32;
        amrow[p] = m < M_NODES ? m : M_NODES - 1;
    }

    float acc[2][8][4];
#pragma unroll
    for (int mi = 0; mi < 2; mi++)
#pragma unroll
        for (int ni = 0; ni < 8; ni++)
#pragma unroll
            for (int j = 0; j < 4; j++) acc[mi][ni][j] = 0.0f;

    unsigned aS[2], bS[2];
    aS[0] = su32(smraw);            bS[0] = su32(smraw + 16384);
    aS[1] = su32(smraw + 32768);    bS[1] = su32(smraw + 49152);

    auto issue = [&](int c, int st) {
        int koff = c * BK;
        unsigned char* As = smraw + st * 32768;
        unsigned char* Bs = smraw + st * 32768 + 16384;
#pragma unroll
        for (int p = 0; p < 4; p++) {
            int row = lrow + p * 32;
            unsigned so = swz((unsigned)(row * 128 + lseg * 16));
            cp16(As + so, A  + (size_t)amrow[p] * HID + koff + lseg * 8);
            cp16(Bs + so, Wt + (size_t)(1536 + n0 + row) * HID + koff + lseg * 8);
        }
        CP_COMMIT();
    };

    issue(0, 0);

    for (int c = 0; c < NCHUNK; ++c) {
        int st = c & 1;
        if (c + 1 < NCHUNK) { issue(c + 1, st ^ 1); CP_WAIT(1); }
        else                { CP_WAIT(0); }
        __syncthreads();

        unsigned ab = aS[st], bb = bS[st];
#pragma unroll
        for (int ks = 0; ks < 4; ++ks) {
            unsigned a[2][4], b[4][4];
#pragma unroll
            for (int mi = 0; mi < 2; mi++) {
                int row = wm * 32 + mi * 16 + (lane & 15);
                unsigned off = (unsigned)(row * 128 + ks * 32 + (lane >> 4) * 16);
                ldsm4(a[mi], ab + swz(off));
            }
#pragma unroll
            for (int nj = 0; nj < 4; nj++) {
                int q = lane >> 3, r2 = lane & 7;
                int nrow = wn * 64 + nj * 16 + (q >> 1) * 8 + r2;
                unsigned off = (unsigned)(nrow * 128 + ks * 32 + (q & 1) * 16);
                ldsm4(b[nj], bb + swz(off));
            }
#pragma unroll
            for (int mi = 0; mi < 2; mi++)
#pragma unroll
                for (int ni = 0; ni < 8; ni++)
                    mma16816(acc[mi][ni], a[mi], b[ni >> 1][(ni & 1) * 2], b[ni >> 1][(ni & 1) * 2 + 1]);
        }
        __syncthreads();
    }

    const int cb = 1536 + n0 + wn * 64 + (lane & 3) * 2;
#pragma unroll
    for (int mi = 0; mi < 2; mi++) {
        int r0 = m0 + wm * 32 + mi * 16 + (lane >> 2);
        int r1 = r0 + 8;
        if (r0 < M_NODES) {
            __half* dst = msg + (size_t)r0 * NMSG + cb;
#pragma unroll
            for (int ni = 0; ni < 8; ni++)
                __stcs((__half2*)(dst + ni * 8), __floats2half2_rn(acc[mi][ni][0], acc[mi][ni][1]));
        }
        if (r1 < M_NODES) {
            __half* dst = msg + (size_t)r1 * NMSG + cb;
#pragma unroll
            for (int ni = 0; ni < 8; ni++)
                __stcs((__half2*)(dst + ni * 8), __floats2half2_rn(acc[mi][ni][2], acc[mi][ni][3]));
        }
    }
}

// ---------------- gather + combine: warp per node, x4 unroll, .cs streaming loads ----------------
__global__ __launch_bounds__(256)
void gather_kernel(const __half* __restrict__ msg, const int* __restrict__ off,
                   const int* __restrict__ eidx, const float* __restrict__ invd,
                   const float* __restrict__ bias, __half* __restrict__ hout)
{
    int node = blockIdx.x * 8 + (threadIdx.x >> 5);
    if (node >= M_NODES) return;
    const int lane = threadIdx.x & 31;

    int beg = __ldg(&off[node]);
    int end = __ldg(&off[node + 1]);

    float acc[8];
#pragma unroll
    for (int j = 0; j < 8; j++) acc[j] = 0.0f;

    auto accum = [&](uint4 u) {
        const __half2* h2 = (const __half2*)&u;
#pragma unroll
        for (int k = 0; k < 4; k++) {
            float2 f = __half22float2(h2[k]);
            acc[2 * k]     += f.x;
            acc[2 * k + 1] += f.y;
        }
    };
    auto rowptr = [&](int pk) {
        return (const uint4*)(msg + (size_t)(pk >> 3) * NMSG + (pk & 7) * HID + lane * 8);
    };

    int e = beg;
    for (; e + 3 < end; e += 4) {
        uint4 u0 = __ldcs(rowptr(__ldg(&eidx[e])));
        uint4 u1 = __ldcs(rowptr(__ldg(&eidx[e + 1])));
        uint4 u2 = __ldcs(rowptr(__ldg(&eidx[e + 2])));
        uint4 u3 = __ldcs(rowptr(__ldg(&eidx[e + 3])));
        accum(u0); accum(u1); accum(u2); accum(u3);
    }
    for (; e < end; ++e)
        accum(__ldcs(rowptr(__ldg(&eidx[e]))));

    float w = invd[node];
    uint4 s = __ldcs((const uint4*)(msg + (size_t)node * NMSG + 1536 + lane * 8));
    const __half2* s2 = (const __half2*)&s;
    float4 b0 = *(const float4*)(bias + lane * 8);
    float4 b1 = *(const float4*)(bias + lane * 8 + 4);
    float bb[8] = {b0.x, b0.y, b0.z, b0.w, b1.x, b1.y, b1.z, b1.w};

    uint4 outv;
    __half2* o2 = (__half2*)&outv;
#pragma unroll
    for (int k = 0; k < 4; k++) {
        float2 sf = __half22float2(s2[k]);
        float v0 = fmaxf(acc[2 * k]     * w + sf.x + bb[2 * k],     0.f);
        float v1 = fmaxf(acc[2 * k + 1] * w + sf.y + bb[2 * k + 1], 0.f);
        o2[k] = __floats2half2_rn(v0, v1);
    }
    *(uint4*)(hout + (size_t)node * HID + lane * 8) = outv;
}

// ---------------- pooling + MLP ----------------
__global__ void count_kernel(const int* __restrict__ bids, int* __restrict__ counts)
{
    int g = threadIdx.x;
    if (g >= NGRAPH) return;
    int lo = 0, hi = M_NODES;
    while (lo < hi) { int mid = (lo + hi) >> 1; if (bids[mid] < g) lo = mid + 1; else hi = mid; }
    int start = lo;
    lo = 0; hi = M_NODES;
    while (lo < hi) { int mid = (lo + hi) >> 1; if (bids[mid] <= g) lo = mid + 1; else hi = mid; }
    counts[g] = lo - start;
}

__global__ void pool_sum_kernel(const __half* __restrict__ h, const int* __restrict__ bids,
                                float* __restrict__ pooled)
{
    int c = threadIdx.x;
    int n_start = blockIdx.x * 256;
    int n_end = n_start + 256;
    if (n_end > M_NODES) n_end = M_NODES;
    if (n_start >= M_NODES) return;
    int cur = bids[n_start];
    float acc = 0.0f;
    for (int n = n_start; n < n_end; n++) {
        int g = bids[n];
        if (g != cur) { atomicAdd(&pooled[cur * HID + c], acc); acc = 0.0f; cur = g; }
        acc += __half2float(h[(size_t)n * HID + c]);
    }
    atomicAdd(&pooled[cur * HID + c], acc);
}

__global__ void mlp_kernel(const float* __restrict__ pooled, const int* __restrict__ counts,
                           const float* __restrict__ pW1, const float* __restrict__ pb1,
                           const float* __restrict__ pW2, const float* __restrict__ pb2,
                           float* __restrict__ out)
{
    __shared__ float p[HID];
    __shared__ float t[HID];
    int g = blockIdx.x, d = threadIdx.x;
    int cn = counts[g];
    float inv = 1.0f / (float)(cn > 1 ? cn : 1);
    p[d] = pooled[g * HID + d] * inv;
    __syncthreads();
    float a = pb1[d];
#pragma unroll 8
    for (int k = 0; k < HID; k++) a += p[k] * pW1[k * HID + d];
    t[d] = a > 0.f ? a : 0.f;
    __syncthreads();
    float o = pb2[d];
#pragma unroll 8
    for (int k = 0; k < HID; k++) o += t[k] * pW2[k * HID + d];
    out[g * HID + d] = o;
}

// ---------------------------------------------------------------
extern "C" void kernel_launch(void* const* d_in, const int* in_sizes, int n_in,
                              void* d_out, int out_size)
{
    const int*   x_type = (const int*)d_in[0];
    const int*   x_sub  = (const int*)d_in[1];
    const int*   edges  = (const int*)d_in[2];
    const int*   bids   = (const int*)d_in[3];
    const float* temb   = (const float*)d_in[5];
    const float* semb   = (const float*)d_in[6];
    const float* Wrel0  = (const float*)d_in[7];
    const float* Wself0 = (const float*)d_in[8];
    const float* b0     = (const float*)d_in[9];
    const float* Wrel1  = (const float*)d_in[10];
    const float* Wself1 = (const float*)d_in[11];
    const float* b1     = (const float*)d_in[12];
    const float* pW1    = (const float*)d_in[13];
    const float* pb1    = (const float*)d_in[14];
    const float* pW2    = (const float*)d_in[15];
    const float* pb2    = (const float*)d_in[16];
    float* out = (float*)d_out;

    void *phA, *phB, *pmsg, *pWt0, *pWt1, *pinv, *pdeg, *poff, *pbsum1, *pbbase1, *pcur, *peidx;
    void *pflag, *psoff, *pbsum2, *pbbase2, *prowlist, *ppooled, *pcnt;
    cudaGetSymbolAddress(&phA, g_hA16);
    cudaGetSymbolAddress(&phB, g_hB16);
    cudaGetSymbolAddress(&pmsg, g_msg);
    cudaGetSymbolAddress(&pWt0, g_Wt0);
    cudaGetSymbolAddress(&pWt1, g_Wt1);
    cudaGetSymbolAddress(&pinv, g_invdeg);
    cudaGetSymbolAddress(&pdeg, g_deg);
    cudaGetSymbolAddress(&poff, g_off);
    cudaGetSymbolAddress(&pbsum1, g_bsum1);
    cudaGetSymbolAddress(&pbbase1, g_bbase1);
    cudaGetSymbolAddress(&pcur, g_cursor);
    cudaGetSymbolAddress(&peidx, g_eidx);
    cudaGetSymbolAddress(&pflag, g_flag);
    cudaGetSymbolAddress(&psoff, g_soff);
    cudaGetSymbolAddress(&pbsum2, g_bsum2);
    cudaGetSymbolAddress(&pbbase2, g_bbase2);
    cudaGetSymbolAddress(&prowlist, g_rowlist);
    cudaGetSymbolAddress(&ppooled, g_pooled);
    cudaGetSymbolAddress(&pcnt, g_counts);

    cudaFuncSetAttribute(gemm_rel, cudaFuncAttributeMaxDynamicSharedMemorySize, GSMEM);
    cudaFuncSetAttribute(gemm_self, cudaFuncAttributeMaxDynamicSharedMemorySize, GSMEM);

    // ---- fork a side stream for graph prework (depends only on `edges`) ----
    cudaStream_t side;
    cudaEvent_t evFork, evJoin;
    cudaStreamCreateWithFlags(&side, cudaStreamNonBlocking);
    cudaEventCreateWithFlags(&evFork, cudaEventDisableTiming);
    cudaEventCreateWithFlags(&evJoin, cudaEventDisableTiming);

    cudaEventRecord(evFork, 0);
    cudaStreamWaitEvent(side, evFork, 0);

    cudaMemsetAsync(pdeg, 0, M_NODES * sizeof(int), side);
    cudaMemsetAsync(pcur, 0, M_NODES * sizeof(int), side);
    cudaMemsetAsync(pflag, 0, NBIN2 * sizeof(int), side);
    degflag_kernel<<<(NEDGE + 255) / 256, 256, 0, side>>>(edges, (int*)pdeg, (int*)pflag);
    invdeg_kernel<<<(M_NODES + 255) / 256, 256, 0, side>>>((const int*)pdeg, (float*)pinv);
    blocksum_kernel<<<NSCAN1, SCAN_BLK, 0, side>>>((const int*)pdeg, (int*)pbsum1, M_NODES);
    bscan_kernel<<<1, SCAN_BLK, 0, side>>>((const int*)pbsum1, (int*)pbbase1, NSCAN1);
    offsets_kernel<<<NSCAN1, SCAN_BLK, 0, side>>>((const int*)pdeg, (const int*)pbbase1, (int*)poff, M_NODES);
    fill_kernel<<<(NEDGE + 255) / 256, 256, 0, side>>>(edges, (const int*)poff, (int*)pcur, (int*)peidx);
    blocksum_kernel<<<NSCAN2, SCAN_BLK, 0, side>>>((const int*)pflag, (int*)pbsum2, NBIN2);
    bscan_kernel<<<1, SCAN_BLK, 0, side>>>((const int*)pbsum2, (int*)pbbase2, NSCAN2);
    offsets_kernel<<<NSCAN2, SCAN_BLK, 0, side>>>((const int*)pflag, (const int*)pbbase2, (int*)psoff, NBIN2);
    rowlist_kernel<<<(NBIN2 + 255) / 256, 256, 0, side>>>((const int*)pflag, (const int*)psoff, (int*)prowlist);
    cudaEventRecord(evJoin, side);

    // main stream: structure-independent work runs concurrently with prework
    cudaMemsetAsync(ppooled, 0, NGRAPH * HID * sizeof(float));
    embed_kernel<<<(M_NODES * HID + 255) / 256, 256>>>(x_type, x_sub, temb, semb, (__half*)phA);
    convW_kernel<<<(NMSG * HID + 255) / 256, 256>>>(Wrel0, Wself0, (__half*)pWt0);
    convW_kernel<<<(NMSG * HID + 255) / 256, 256>>>(Wrel1, Wself1, (__half*)pWt1);

    dim3 rgrid(2, (M_NODES + BM - 1) / BM, NREL);   // (2, 782, 6), early-exit above cnt
    dim3 sgrid(2, (M_NODES + BM - 1) / BM);         // (2, 782)
    int gblocks = (M_NODES + 7) / 8;

    // ---- layer 0: hA -> hB ----
    gemm_self<<<sgrid, 256, GSMEM>>>((const __half*)phA, (const __half*)pWt0, (__half*)pmsg);
    cudaStreamWaitEvent(0, evJoin, 0);
    gemm_rel<<<rgrid, 256, GSMEM>>>((const __half*)phA, (const __half*)pWt0,
                                    (const int*)psoff, (const int*)prowlist, (__half*)pmsg);
    gather_kernel<<<gblocks, 256>>>((const __half*)pmsg, (const int*)poff, (const int*)peidx,
                                    (const float*)pinv, b0, (__half*)phB);

    // ---- layer 1: hB -> hA ----
    gemm_rel<<<rgrid, 256, GSMEM>>>((const __half*)phB, (const __half*)pWt1,
                                    (const int*)psoff, (const int*)prowlist, (__half*)pmsg);
    gemm_self<<<sgrid, 256, GSMEM>>>((const __half*)phB, (const __half*)pWt1, (__half*)pmsg);
    gather_kernel<<<gblocks, 256>>>((const __half*)pmsg, (const int*)poff, (const int*)peidx,
                                    (const float*)pinv, b1, (__half*)phA);

    // ---- pool + MLP ----
    count_kernel<<<1, 128>>>(bids, (int*)pcnt);
    pool_sum_kernel<<<(M_NODES + 255) / 256, 256>>>((const __half*)phA, bids, (float*)ppooled);
    mlp_kernel<<<NGRAPH, 256>>>((const float*)ppooled, (const int*)pcnt, pW1, pb1, pW2, pb2, out);

    cudaEventDestroy(evFork);
    cudaEventDestroy(evJoin);
    cudaStreamDestroy(side);
}